// round 4
// baseline (speedup 1.0000x reference)
#include <cuda_runtime.h>

#define NLAYERS 4
#define KCODES  1024
#define FDIM    512
#define BM      64
#define BN      128
#define BK      32

// c2[l][k] = ||codebook[l][k]||^2, fp64 accumulate, rounded to fp32.
__device__ float g_c2[NLAYERS * KCODES];

__global__ void c2_kernel(const float* __restrict__ cb) {
    int code = blockIdx.x * 8 + (threadIdx.x >> 5);   // warp per code
    int lane = threadIdx.x & 31;
    if (code >= NLAYERS * KCODES) return;
    const float* row = cb + (size_t)code * FDIM;
    double s = 0.0;
    for (int k = lane; k < FDIM; k += 32) { double v = (double)row[k]; s += v * v; }
    #pragma unroll
    for (int off = 16; off; off >>= 1) s += __shfl_xor_sync(0xffffffffu, s, off);
    if (lane == 0) g_c2[code] = (float)s;
}

// Monotone mapping: ordered-uint of float (total order matching < on floats)
__device__ __forceinline__ unsigned fmono(float f) {
    unsigned u = __float_as_uint(f);
    return (u & 0x80000000u) ? ~u : (u | 0x80000000u);
}

// mode 0: d_out = float[ nrows*NLAYERS codes | nrows*FDIM recon ]
// mode 1: d_out = float[ nrows*FDIM recon ]
// mode 2: d_out = long long[ nrows*NLAYERS codes ]
__global__ __launch_bounds__(256, 1)
void rq_kernel(const float* __restrict__ data, const float* __restrict__ cb,
               void* __restrict__ out_raw, int nrows, int mode) {
    extern __shared__ float smem[];
    float* Rs  = smem;                         // FDIM*BM residual, col-major [k][row]
    float* Bs  = Rs + FDIM * BM;               // BK*BN codebook tile [kk][n]
    float* c2s = Bs + BK * BN;                 // BN
    float* xs2 = c2s + BN;                     // BM
    unsigned long long* best = (unsigned long long*)(xs2 + BM);  // BM packed keys

    const int tid = threadIdx.x;
    const int tx = tid & 15, ty = tid >> 4;    // 16x16 grid; rows ty*4.., cols tx*8..
    const int row0 = blockIdx.x * BM;
    const float4* data4 = (const float4*)data;

    // ---- load data tile -> residual (column-major). OOB rows -> 0. ----
    for (int i = tid; i < BM * (FDIM / 4); i += 256) {
        int r = i & (BM - 1), k4 = i >> 6;
        float4 v = make_float4(0.f, 0.f, 0.f, 0.f);
        if (row0 + r < nrows) v = data4[(size_t)(row0 + r) * (FDIM / 4) + k4];
        Rs[(k4 * 4 + 0) * BM + r] = v.x;
        Rs[(k4 * 4 + 1) * BM + r] = v.y;
        Rs[(k4 * 4 + 2) * BM + r] = v.z;
        Rs[(k4 * 4 + 3) * BM + r] = v.w;
    }
    __syncthreads();

    for (int l = 0; l < NLAYERS; ++l) {
        // ---- x2 per row (fp64 accumulate -> fp32, matching reference value) ----
        if (tid < BM) {
            double s = 0.0;
            for (int k = 0; k < FDIM; ++k) {
                double v = (double)Rs[k * BM + tid];
                s += v * v;
            }
            xs2[tid] = (float)s;
            best[tid] = 0xFFFFFFFFFFFFFFFFull;
        }
        __syncthreads();

        const float4* cbl4 = (const float4*)(cb + (size_t)l * KCODES * FDIM);

        for (int n0 = 0; n0 < KCODES; n0 += BN) {
            float acc[4][8];
            #pragma unroll
            for (int i = 0; i < 4; ++i)
                #pragma unroll
                for (int j = 0; j < 8; ++j) acc[i][j] = 0.f;

            if (tid < BN) c2s[tid] = g_c2[l * KCODES + n0 + tid];

            for (int k0 = 0; k0 < FDIM; k0 += BK) {
                {   // load Bs[kk][n]
                    int n = tid >> 1;
                    int base = (tid & 1) * 4;
                    #pragma unroll
                    for (int j = 0; j < 4; ++j) {
                        int kk4 = base + j;
                        float4 v = cbl4[(size_t)(n0 + n) * (FDIM / 4) + (k0 >> 2) + kk4];
                        Bs[(kk4 * 4 + 0) * BN + n] = v.x;
                        Bs[(kk4 * 4 + 1) * BN + n] = v.y;
                        Bs[(kk4 * 4 + 2) * BN + n] = v.z;
                        Bs[(kk4 * 4 + 3) * BN + n] = v.w;
                    }
                }
                __syncthreads();
                #pragma unroll
                for (int kk = 0; kk < BK; ++kk) {
                    float4 a  = *(const float4*)&Rs[(k0 + kk) * BM + ty * 4];
                    float4 b0 = *(const float4*)&Bs[kk * BN + tx * 8];
                    float4 b1 = *(const float4*)&Bs[kk * BN + tx * 8 + 4];
                    float av[4] = {a.x, a.y, a.z, a.w};
                    float bv[8] = {b0.x, b0.y, b0.z, b0.w, b1.x, b1.y, b1.z, b1.w};
                    #pragma unroll
                    for (int i = 0; i < 4; ++i)
                        #pragma unroll
                        for (int j = 0; j < 8; ++j)
                            acc[i][j] = fmaf(av[i], bv[j], acc[i][j]);
                }
                __syncthreads();
            }

            // ---- fold running argmin: score = fl(fl(x2 + c2) - fl(2*dot)) ----
            #pragma unroll
            for (int i = 0; i < 4; ++i) {
                int r = ty * 4 + i;
                float x2 = xs2[r];
                unsigned long long kbest = 0xFFFFFFFFFFFFFFFFull;
                #pragma unroll
                for (int j = 0; j < 8; ++j) {
                    int idx = n0 + tx * 8 + j;
                    float sc = __fsub_rn(__fadd_rn(x2, c2s[tx * 8 + j]),
                                         __fmul_rn(2.0f, acc[i][j]));
                    unsigned long long key =
                        ((unsigned long long)fmono(sc) << 32) | (unsigned)idx;
                    kbest = (key < kbest) ? key : kbest;
                }
                atomicMin(&best[r], kbest);
            }
            __syncthreads();
        }

        // ---- residual -= codebook[bestIdx]; emit code ----
        for (int i = tid; i < BM * (FDIM / 4); i += 256) {
            int r = i & (BM - 1), k4 = i >> 6;
            unsigned idx = (unsigned)(best[r] & 0xFFFFFFFFull);
            float4 v = cbl4[(size_t)idx * (FDIM / 4) + k4];
            Rs[(k4 * 4 + 0) * BM + r] -= v.x;
            Rs[(k4 * 4 + 1) * BM + r] -= v.y;
            Rs[(k4 * 4 + 2) * BM + r] -= v.z;
            Rs[(k4 * 4 + 3) * BM + r] -= v.w;
        }
        if (tid < BM && row0 + tid < nrows) {
            unsigned idx = (unsigned)(best[tid] & 0xFFFFFFFFull);
            size_t o = (size_t)(row0 + tid) * NLAYERS + l;
            if (mode == 0)      ((float*)out_raw)[o] = (float)idx;
            else if (mode == 2) ((long long*)out_raw)[o] = (long long)idx;
        }
        __syncthreads();
    }

    // ---- recon = data - residual ----
    if (mode != 2) {
        float* out_recon = (float*)out_raw;
        if (mode == 0) out_recon += (size_t)nrows * NLAYERS;
        for (int i = tid; i < BM * (FDIM / 4); i += 256) {
            int r = i & (BM - 1), k4 = i >> 6;
            if (row0 + r < nrows) {
                float4 d = data4[(size_t)(row0 + r) * (FDIM / 4) + k4];
                size_t o = (size_t)(row0 + r) * FDIM + (size_t)k4 * 4;
                out_recon[o + 0] = d.x - Rs[(k4 * 4 + 0) * BM + r];
                out_recon[o + 1] = d.y - Rs[(k4 * 4 + 1) * BM + r];
                out_recon[o + 2] = d.z - Rs[(k4 * 4 + 2) * BM + r];
                out_recon[o + 3] = d.w - Rs[(k4 * 4 + 3) * BM + r];
            }
        }
    }
}

extern "C" void kernel_launch(void* const* d_in, const int* in_sizes, int n_in,
                              void* d_out, int out_size) {
    const float* data = (const float*)d_in[0];           // [N, 512] f32
    const float* cb   = (const float*)d_in[1];           // [4, 1024, 512] f32
    int nrows = in_sizes[0] / FDIM;

    // Decide output layout from out_size (element count of unknown dtype).
    long long n_both  = (long long)nrows * (NLAYERS + FDIM);
    long long n_recon = (long long)nrows * FDIM;
    long long n_codes = (long long)nrows * NLAYERS;
    int mode = 0;                                        // default: codes | recon (f32)
    if ((long long)out_size == n_recon)      mode = 1;   // recon only (f32)
    else if ((long long)out_size == n_codes) mode = 2;   // codes only (int64)
    else if ((long long)out_size == n_both)  mode = 0;

    const size_t smem_bytes = (size_t)(FDIM * BM + BK * BN + BN + BM) * sizeof(float)
                            + (size_t)BM * sizeof(unsigned long long);
    cudaFuncSetAttribute(rq_kernel, cudaFuncAttributeMaxDynamicSharedMemorySize,
                         (int)smem_bytes);

    c2_kernel<<<(NLAYERS * KCODES + 7) / 8, 256>>>(cb);
    rq_kernel<<<(nrows + BM - 1) / BM, 256, smem_bytes>>>(data, cb, d_out,
                                                          nrows, mode);
}

// round 5
// speedup vs baseline: 1.0004x; 1.0004x over previous
#include <cuda_runtime.h>

#define NLAYERS 4
#define KCODES  1024
#define FDIM    512
#define BM      64
#define BN      128
#define BK      32

// c2[l][k] = ||codebook[l][k]||^2, fp64 accumulate, rounded to fp32.
__device__ float g_c2[NLAYERS * KCODES];

__global__ void c2_kernel(const float* __restrict__ cb) {
    int code = blockIdx.x * 8 + (threadIdx.x >> 5);   // warp per code
    int lane = threadIdx.x & 31;
    if (code >= NLAYERS * KCODES) return;
    const float* row = cb + (size_t)code * FDIM;
    double s = 0.0;
    for (int k = lane; k < FDIM; k += 32) { double v = (double)row[k]; s += v * v; }
    #pragma unroll
    for (int off = 16; off; off >>= 1) s += __shfl_xor_sync(0xffffffffu, s, off);
    if (lane == 0) g_c2[code] = (float)s;
}

// Monotone mapping: ordered-uint of float (total order matching < on floats)
__device__ __forceinline__ unsigned fmono(float f) {
    unsigned u = __float_as_uint(f);
    return (u & 0x80000000u) ? ~u : (u | 0x80000000u);
}

// mode 0: d_out = float[ nrows*NLAYERS codes | nrows*FDIM recon ]
// mode 1: d_out = float[ nrows*FDIM recon ]
// mode 2: d_out = long long[ nrows*NLAYERS codes ]
__global__ __launch_bounds__(256, 1)
void rq_kernel(const float* __restrict__ data, const float* __restrict__ cb,
               void* __restrict__ out_raw, int nrows, int mode) {
    extern __shared__ float smem[];
    float* Rs  = smem;                         // FDIM*BM residual, col-major [k][row]
    float* Bs  = Rs + FDIM * BM;               // BK*BN codebook tile [kk][n]
    float* c2s = Bs + BK * BN;                 // BN
    float* xs2 = c2s + BN;                     // BM
    unsigned long long* best = (unsigned long long*)(xs2 + BM);  // BM packed keys

    const int tid = threadIdx.x;
    const int tx = tid & 15, ty = tid >> 4;    // 16x16 grid; rows ty*4.., cols tx*8..
    const int row0 = blockIdx.x * BM;
    const float4* data4 = (const float4*)data;

    // ---- load data tile -> residual (column-major). OOB rows -> 0. ----
    for (int i = tid; i < BM * (FDIM / 4); i += 256) {
        int r = i & (BM - 1), k4 = i >> 6;
        float4 v = make_float4(0.f, 0.f, 0.f, 0.f);
        if (row0 + r < nrows) v = data4[(size_t)(row0 + r) * (FDIM / 4) + k4];
        Rs[(k4 * 4 + 0) * BM + r] = v.x;
        Rs[(k4 * 4 + 1) * BM + r] = v.y;
        Rs[(k4 * 4 + 2) * BM + r] = v.z;
        Rs[(k4 * 4 + 3) * BM + r] = v.w;
    }
    __syncthreads();

    for (int l = 0; l < NLAYERS; ++l) {
        // ---- x2 per row (fp64 accumulate -> fp32, matching reference value) ----
        if (tid < BM) {
            double s = 0.0;
            for (int k = 0; k < FDIM; ++k) {
                double v = (double)Rs[k * BM + tid];
                s += v * v;
            }
            xs2[tid] = (float)s;
            best[tid] = 0xFFFFFFFFFFFFFFFFull;
        }
        __syncthreads();

        const float4* cbl4 = (const float4*)(cb + (size_t)l * KCODES * FDIM);

        for (int n0 = 0; n0 < KCODES; n0 += BN) {
            float acc[4][8];
            #pragma unroll
            for (int i = 0; i < 4; ++i)
                #pragma unroll
                for (int j = 0; j < 8; ++j) acc[i][j] = 0.f;

            if (tid < BN) c2s[tid] = g_c2[l * KCODES + n0 + tid];

            for (int k0 = 0; k0 < FDIM; k0 += BK) {
                {   // load Bs[kk][n]
                    int n = tid >> 1;
                    int base = (tid & 1) * 4;
                    #pragma unroll
                    for (int j = 0; j < 4; ++j) {
                        int kk4 = base + j;
                        float4 v = cbl4[(size_t)(n0 + n) * (FDIM / 4) + (k0 >> 2) + kk4];
                        Bs[(kk4 * 4 + 0) * BN + n] = v.x;
                        Bs[(kk4 * 4 + 1) * BN + n] = v.y;
                        Bs[(kk4 * 4 + 2) * BN + n] = v.z;
                        Bs[(kk4 * 4 + 3) * BN + n] = v.w;
                    }
                }
                __syncthreads();
                #pragma unroll
                for (int kk = 0; kk < BK; ++kk) {
                    float4 a  = *(const float4*)&Rs[(k0 + kk) * BM + ty * 4];
                    float4 b0 = *(const float4*)&Bs[kk * BN + tx * 8];
                    float4 b1 = *(const float4*)&Bs[kk * BN + tx * 8 + 4];
                    float av[4] = {a.x, a.y, a.z, a.w};
                    float bv[8] = {b0.x, b0.y, b0.z, b0.w, b1.x, b1.y, b1.z, b1.w};
                    #pragma unroll
                    for (int i = 0; i < 4; ++i)
                        #pragma unroll
                        for (int j = 0; j < 8; ++j)
                            acc[i][j] = fmaf(av[i], bv[j], acc[i][j]);
                }
                __syncthreads();
            }

            // ---- fold running argmin: score = fl(fl(x2 + c2) - fl(2*dot)) ----
            #pragma unroll
            for (int i = 0; i < 4; ++i) {
                int r = ty * 4 + i;
                float x2 = xs2[r];
                unsigned long long kbest = 0xFFFFFFFFFFFFFFFFull;
                #pragma unroll
                for (int j = 0; j < 8; ++j) {
                    int idx = n0 + tx * 8 + j;
                    float sc = __fsub_rn(__fadd_rn(x2, c2s[tx * 8 + j]),
                                         __fmul_rn(2.0f, acc[i][j]));
                    unsigned long long key =
                        ((unsigned long long)fmono(sc) << 32) | (unsigned)idx;
                    kbest = (key < kbest) ? key : kbest;
                }
                atomicMin(&best[r], kbest);
            }
            __syncthreads();
        }

        // ---- residual -= codebook[bestIdx]; emit code ----
        for (int i = tid; i < BM * (FDIM / 4); i += 256) {
            int r = i & (BM - 1), k4 = i >> 6;
            unsigned idx = (unsigned)(best[r] & 0xFFFFFFFFull);
            float4 v = cbl4[(size_t)idx * (FDIM / 4) + k4];
            Rs[(k4 * 4 + 0) * BM + r] -= v.x;
            Rs[(k4 * 4 + 1) * BM + r] -= v.y;
            Rs[(k4 * 4 + 2) * BM + r] -= v.z;
            Rs[(k4 * 4 + 3) * BM + r] -= v.w;
        }
        if (tid < BM && row0 + tid < nrows) {
            unsigned idx = (unsigned)(best[tid] & 0xFFFFFFFFull);
            size_t o = (size_t)(row0 + tid) * NLAYERS + l;
            if (mode == 0)      ((float*)out_raw)[o] = (float)idx;
            else if (mode == 2) ((long long*)out_raw)[o] = (long long)idx;
        }
        __syncthreads();
    }

    // ---- recon = data - residual ----
    if (mode != 2) {
        float* out_recon = (float*)out_raw;
        if (mode == 0) out_recon += (size_t)nrows * NLAYERS;
        for (int i = tid; i < BM * (FDIM / 4); i += 256) {
            int r = i & (BM - 1), k4 = i >> 6;
            if (row0 + r < nrows) {
                float4 d = data4[(size_t)(row0 + r) * (FDIM / 4) + k4];
                size_t o = (size_t)(row0 + r) * FDIM + (size_t)k4 * 4;
                out_recon[o + 0] = d.x - Rs[(k4 * 4 + 0) * BM + r];
                out_recon[o + 1] = d.y - Rs[(k4 * 4 + 1) * BM + r];
                out_recon[o + 2] = d.z - Rs[(k4 * 4 + 2) * BM + r];
                out_recon[o + 3] = d.w - Rs[(k4 * 4 + 3) * BM + r];
            }
        }
    }
}

extern "C" void kernel_launch(void* const* d_in, const int* in_sizes, int n_in,
                              void* d_out, int out_size) {
    const float* data = (const float*)d_in[0];           // [N, 512] f32
    const float* cb   = (const float*)d_in[1];           // [4, 1024, 512] f32
    int nrows = in_sizes[0] / FDIM;

    // Decide output layout from out_size (element count of unknown dtype).
    long long n_both  = (long long)nrows * (NLAYERS + FDIM);
    long long n_recon = (long long)nrows * FDIM;
    long long n_codes = (long long)nrows * NLAYERS;
    int mode = 0;                                        // default: codes | recon (f32)
    if ((long long)out_size == n_recon)      mode = 1;   // recon only (f32)
    else if ((long long)out_size == n_codes) mode = 2;   // codes only (int64)
    else if ((long long)out_size == n_both)  mode = 0;

    const size_t smem_bytes = (size_t)(FDIM * BM + BK * BN + BN + BM) * sizeof(float)
                            + (size_t)BM * sizeof(unsigned long long);
    cudaFuncSetAttribute(rq_kernel, cudaFuncAttributeMaxDynamicSharedMemorySize,
                         (int)smem_bytes);

    c2_kernel<<<(NLAYERS * KCODES + 7) / 8, 256>>>(cb);
    rq_kernel<<<(nrows + BM - 1) / BM, 256, smem_bytes>>>(data, cb, d_out,
                                                          nrows, mode);
}

// round 10
// speedup vs baseline: 1.5871x; 1.5865x over previous
#include <cuda_runtime.h>
#include <cuda_bf16.h>
#include <cstdint>

#define NLAYERS 4
#define KCODES  1024
#define FDIM    512
#define BM      128
#define BN      128
#define KT      64
#define NSTK    (FDIM / KT)      // 8 k-tiles
#define NCHUNK  (KCODES / BN)    // 8 n-chunks
#define NSTEPS  (NCHUNK * NSTK)  // 64
#define MAXR    100352

// ---------------- global scratch ----------------
__device__ __align__(16) float          g_R  [(size_t)MAXR * FDIM];
__device__ __align__(16) __nv_bfloat16  g_Rhi[(size_t)MAXR * FDIM];
__device__ __align__(16) __nv_bfloat16  g_Rmd[(size_t)MAXR * FDIM];
__device__ __align__(16) __nv_bfloat16  g_Rlo[(size_t)MAXR * FDIM];
__device__ float g_x2[MAXR];
__device__ __align__(16) __nv_bfloat16  g_Chi[NLAYERS * KCODES * FDIM];
__device__ __align__(16) __nv_bfloat16  g_Cmd[NLAYERS * KCODES * FDIM];
__device__ __align__(16) __nv_bfloat16  g_Clo[NLAYERS * KCODES * FDIM];
__device__ float g_c2[NLAYERS * KCODES];

// ---------------- helpers ----------------
__device__ __forceinline__ uint32_t smem_u32(const void* p) {
    uint32_t a;
    asm("{ .reg .u64 t; cvta.to.shared.u64 t, %1; cvt.u32.u64 %0, t; }" : "=r"(a) : "l"(p));
    return a;
}
#define SWZ128(o) ((o) ^ (((o) >> 3) & 0x70))

__device__ __forceinline__ void cp_async16(uint32_t saddr, const void* gaddr) {
    asm volatile("cp.async.cg.shared.global [%0], [%1], 16;"
                 :: "r"(saddr), "l"(gaddr) : "memory");
}
#define CP_COMMIT() asm volatile("cp.async.commit_group;" ::: "memory")
#define CP_WAIT1()  asm volatile("cp.async.wait_group 1;" ::: "memory")
#define CP_WAIT0()  asm volatile("cp.async.wait_group 0;" ::: "memory")

__device__ __forceinline__ void ldm_x4(uint32_t* r, uint32_t addr) {
    asm volatile("ldmatrix.sync.aligned.m8n8.x4.shared.b16 {%0,%1,%2,%3}, [%4];"
                 : "=r"(r[0]), "=r"(r[1]), "=r"(r[2]), "=r"(r[3]) : "r"(addr));
}
__device__ __forceinline__ void mma16816(float* c, const uint32_t* a,
                                         uint32_t b0, uint32_t b1) {
    asm volatile("mma.sync.aligned.m16n8k16.row.col.f32.bf16.bf16.f32 "
                 "{%0,%1,%2,%3}, {%4,%5,%6,%7}, {%8,%9}, {%0,%1,%2,%3};"
                 : "+f"(c[0]), "+f"(c[1]), "+f"(c[2]), "+f"(c[3])
                 : "r"(a[0]), "r"(a[1]), "r"(a[2]), "r"(a[3]), "r"(b0), "r"(b1));
}

__device__ __forceinline__ unsigned fmono(float f) {
    unsigned u = __float_as_uint(f);
    return (u & 0x80000000u) ? ~u : (u | 0x80000000u);
}
__device__ __forceinline__ void split3(float x, __nv_bfloat16& h, __nv_bfloat16& m,
                                       __nv_bfloat16& l) {
    h = __float2bfloat16(x);
    float r1 = x - __bfloat162float(h);
    m = __float2bfloat16(r1);
    float r2 = r1 - __bfloat162float(m);
    l = __float2bfloat16(r2);
}

// ---------------- prep kernels ----------------
__global__ void cbprep_kernel(const float* __restrict__ cb) {
    size_t i0 = ((size_t)blockIdx.x * 256 + threadIdx.x) * 4;
    if (i0 >= (size_t)NLAYERS * KCODES * FDIM) return;
    #pragma unroll
    for (int j = 0; j < 4; ++j) {
        size_t i = i0 + j;
        __nv_bfloat16 h, m, l;
        split3(cb[i], h, m, l);
        g_Chi[i] = h; g_Cmd[i] = m; g_Clo[i] = l;
    }
}

__global__ void c2_kernel(const float* __restrict__ cb) {
    int code = blockIdx.x * 8 + (threadIdx.x >> 5);
    int lane = threadIdx.x & 31;
    if (code >= NLAYERS * KCODES) return;
    const float* row = cb + (size_t)code * FDIM;
    double s = 0.0;
    for (int k = lane; k < FDIM; k += 32) { double v = (double)row[k]; s += v * v; }
    #pragma unroll
    for (int off = 16; off; off >>= 1) s += __shfl_xor_sync(0xffffffffu, s, off);
    if (lane == 0) g_c2[code] = (float)s;
}

__global__ void init_kernel(const float* __restrict__ data, int nrows) {
    int r = blockIdx.x * 8 + (threadIdx.x >> 5);
    int lane = threadIdx.x & 31;
    if (r >= nrows) return;
    const float4* src = (const float4*)(data + (size_t)r * FDIM);
    float4* Rr = (float4*)(g_R + (size_t)r * FDIM);
    double ss = 0.0;
    #pragma unroll
    for (int j = 0; j < 4; ++j) {
        int q = lane + 32 * j;
        float4 v = src[q];
        Rr[q] = v;
        float vv[4] = {v.x, v.y, v.z, v.w};
        __nv_bfloat16 h[4], m[4], l[4];
        #pragma unroll
        for (int c = 0; c < 4; ++c) {
            split3(vv[c], h[c], m[c], l[c]);
            ss += (double)vv[c] * vv[c];
        }
        size_t e = (size_t)r * FDIM + (size_t)q * 4;
        __nv_bfloat162 t;
        t.x=h[0]; t.y=h[1]; *(__nv_bfloat162*)(g_Rhi+e)   = t;
        t.x=h[2]; t.y=h[3]; *(__nv_bfloat162*)(g_Rhi+e+2) = t;
        t.x=m[0]; t.y=m[1]; *(__nv_bfloat162*)(g_Rmd+e)   = t;
        t.x=m[2]; t.y=m[3]; *(__nv_bfloat162*)(g_Rmd+e+2) = t;
        t.x=l[0]; t.y=l[1]; *(__nv_bfloat162*)(g_Rlo+e)   = t;
        t.x=l[2]; t.y=l[3]; *(__nv_bfloat162*)(g_Rlo+e+2) = t;
    }
    #pragma unroll
    for (int off = 16; off; off >>= 1) ss += __shfl_xor_sync(0xffffffffu, ss, off);
    if (lane == 0) g_x2[r] = (float)ss;
}

// ---------------- layer kernel ----------------
// smem map (bytes):
//   [0,512)       x2s float[128]
//   [512,4608)    c2s float[1024]
//   [4608,8704)   top u64[128][2][2]  (per row, per warp-column: top-2 keys)
//   [8704,9216)   bidx u32[128]
//   [10240,...)   tiles: 2 stages x 6 tiles x 16384 (tile = 128 rows x 128B, SW128)
#define SM_X2   0
#define SM_C2   512
#define SM_TOP  4608
#define SM_BIDX 8704
#define SM_TILE 10240
#define TILE_SZ 16384
#define TILE_OFF(stg, t) (SM_TILE + ((stg) * 6 + (t)) * TILE_SZ)
#define SMEM_TOTAL (SM_TILE + 12 * TILE_SZ)   // 206848 B

__global__ __launch_bounds__(256, 1)
void layer_kernel(const float* __restrict__ cb, const float* __restrict__ data,
                  void* __restrict__ out_raw, int nrows, int layer, int mode) {
    extern __shared__ char smem[];
    const uint32_t sb = smem_u32(smem);
    const int tid = threadIdx.x, wid = tid >> 5, lane = tid & 31;
    const int wm = wid & 3, wn = wid >> 2;     // 4 warps M x 2 warps N
    const int row0 = blockIdx.x * BM;

    float* x2s = (float*)(smem + SM_X2);
    float* c2s = (float*)(smem + SM_C2);
    unsigned long long* topsm = (unsigned long long*)(smem + SM_TOP);

    for (int i = tid; i < KCODES; i += 256) c2s[i] = g_c2[layer * KCODES + i];
    if (tid < BM) {
        int r = min(row0 + tid, nrows - 1);
        x2s[tid] = g_x2[r];
    }
    __syncthreads();

    const __nv_bfloat16* asrc[3] = {g_Rhi, g_Rmd, g_Rlo};
    const __nv_bfloat16* bsrc[3] = {g_Chi, g_Cmd, g_Clo};

    auto load_stage = [&](int stg, int chunk, int ktile) {
        const int n0 = chunk * BN;
        #pragma unroll
        for (int t = 0; t < 6; ++t) {
            const __nv_bfloat16* src = (t < 3) ? asrc[t] : bsrc[t - 3];
            const uint32_t base = sb + TILE_OFF(stg, t);
            #pragma unroll
            for (int j = 0; j < 4; ++j) {
                int i = tid + 256 * j;
                int row = i >> 3, c16 = i & 7;
                int rg = (t < 3) ? min(row0 + row, nrows - 1)
                                 : (layer * KCODES + n0 + row);
                const void* g = src + (size_t)rg * FDIM + ktile * KT + c16 * 8;
                cp_async16(base + SWZ128(row * 128 + c16 * 16), g);
            }
        }
    };

    float acc[2][8][4];
    #pragma unroll
    for (int mf = 0; mf < 2; ++mf)
        #pragma unroll
        for (int nf = 0; nf < 8; ++nf)
            #pragma unroll
            for (int q = 0; q < 4; ++q) acc[mf][nf][q] = 0.f;

    // per-lane running top-2 for 4 row-slots: s = mf*2 + (0:rowA, 1:rowB)
    unsigned long long tk1[4], tk2[4];
    #pragma unroll
    for (int s = 0; s < 4; ++s) { tk1[s] = ~0ull; tk2[s] = ~0ull; }

    load_stage(0, 0, 0);
    CP_COMMIT();

    const int ca6[6] = {0, 0, 1, 1, 0, 2};
    const int cb6[6] = {0, 1, 0, 1, 2, 0};

    for (int step = 0; step < NSTEPS; ++step) {
        const int chunk = step >> 3, ktile = step & 7, stg = step & 1;
        if (step + 1 < NSTEPS) {
            load_stage(stg ^ 1, (step + 1) >> 3, (step + 1) & 7);
            CP_COMMIT();
            CP_WAIT1();
        } else {
            CP_WAIT0();
        }
        __syncthreads();

        // ---- MMA over 6 split products, 4 k16 steps ----
        #pragma unroll
        for (int c6 = 0; c6 < 6; ++c6) {
            const uint32_t abase = sb + TILE_OFF(stg, ca6[c6]);
            const uint32_t bbase = sb + TILE_OFF(stg, 3 + cb6[c6]);
            #pragma unroll
            for (int ks = 0; ks < 4; ++ks) {
                uint32_t afr[2][4];
                #pragma unroll
                for (int mf = 0; mf < 2; ++mf) {
                    int arow = wm * 32 + mf * 16 + (lane & 15);
                    int akc  = ks * 2 + (lane >> 4);
                    ldm_x4(afr[mf], abase + SWZ128(arow * 128 + akc * 16));
                }
                #pragma unroll
                for (int nf2 = 0; nf2 < 4; ++nf2) {
                    uint32_t bfr[4];
                    int g = lane >> 3;
                    int brow = wn * 64 + nf2 * 16 + ((g >> 1) << 3) + (lane & 7);
                    int bkc  = ks * 2 + (g & 1);
                    ldm_x4(bfr, bbase + SWZ128(brow * 128 + bkc * 16));
                    mma16816(acc[0][nf2 * 2 + 0], afr[0], bfr[0], bfr[1]);
                    mma16816(acc[0][nf2 * 2 + 1], afr[0], bfr[2], bfr[3]);
                    mma16816(acc[1][nf2 * 2 + 0], afr[1], bfr[0], bfr[1]);
                    mma16816(acc[1][nf2 * 2 + 1], afr[1], bfr[2], bfr[3]);
                }
            }
        }

        // ---- per-chunk epilogue: approx score, fold per-lane top-2 ----
        if (ktile == 7) {
            const int n0 = chunk * BN;
            #pragma unroll
            for (int mf = 0; mf < 2; ++mf) {
                int rA = wm * 32 + mf * 16 + (lane >> 2);
                int rB = rA + 8;
                float x2A = x2s[rA], x2B = x2s[rB];
                #pragma unroll
                for (int nf = 0; nf < 8; ++nf) {
                    int col = wn * 64 + nf * 8 + (lane & 3) * 2;
                    #pragma unroll
                    for (int e = 0; e < 2; ++e) {
                        int idxc = n0 + col + e;
                        float cc = c2s[idxc];
                        float scA = __fsub_rn(__fadd_rn(x2A, cc),
                                              __fmul_rn(2.0f, acc[mf][nf][e]));
                        float scB = __fsub_rn(__fadd_rn(x2B, cc),
                                              __fmul_rn(2.0f, acc[mf][nf][2 + e]));
                        unsigned long long keyA =
                            ((unsigned long long)fmono(scA) << 32) | (unsigned)idxc;
                        unsigned long long keyB =
                            ((unsigned long long)fmono(scB) << 32) | (unsigned)idxc;
                        int sA = mf * 2, sB = mf * 2 + 1;
                        if (keyA < tk1[sA]) { tk2[sA] = tk1[sA]; tk1[sA] = keyA; }
                        else if (keyA < tk2[sA]) tk2[sA] = keyA;
                        if (keyB < tk1[sB]) { tk2[sB] = tk1[sB]; tk1[sB] = keyB; }
                        else if (keyB < tk2[sB]) tk2[sB] = keyB;
                    }
                }
                #pragma unroll
                for (int nf = 0; nf < 8; ++nf)
                    #pragma unroll
                    for (int q = 0; q < 4; ++q) acc[mf][nf][q] = 0.f;
            }
        }
        __syncthreads();
    }

    // ---- quad merge of per-lane top-2 -> smem per (row, wn) ----
    #pragma unroll
    for (int s = 0; s < 4; ++s) {
        unsigned long long a = tk1[s], b = tk2[s];
        #pragma unroll
        for (int off = 1; off <= 2; off <<= 1) {
            unsigned long long oa = __shfl_xor_sync(0xffffffffu, a, off);
            unsigned long long ob = __shfl_xor_sync(0xffffffffu, b, off);
            unsigned long long n1 = (a < oa) ? a : oa;
            unsigned long long hi = (a < oa) ? oa : a;
            unsigned long long lo2 = (b < ob) ? b : ob;
            b = (hi < lo2) ? hi : lo2;
            a = n1;
        }
        if ((lane & 3) == 0) {
            int row = wm * 32 + (s >> 1) * 16 + (lane >> 2) + (s & 1) * 8;
            topsm[row * 4 + wn * 2 + 0] = a;
            topsm[row * 4 + wn * 2 + 1] = b;
        }
    }
    __syncthreads();

    // ---- fp64 exact rescore of top-2 candidates (warp per row) ----
    const float* cbl = cb + (size_t)layer * KCODES * FDIM;
    for (int m = wid; m < BM; m += 8) {
        if (row0 + m >= nrows) continue;
        unsigned long long t0 = topsm[m * 4 + 0], t1 = topsm[m * 4 + 1];
        unsigned long long t2 = topsm[m * 4 + 2], t3 = topsm[m * 4 + 3];
        unsigned long long a = (t0 < t2) ? t0 : t2, b = (t0 < t2) ? t2 : t0;
        unsigned long long c = (t1 < t3) ? t1 : t3, d = (t1 < t3) ? t3 : t1;
        unsigned long long m1 = (a < c) ? a : c;
        unsigned long long hi = (a < c) ? c : a;
        unsigned long long lo2 = (b < d) ? b : d;
        unsigned long long m2 = (hi < lo2) ? hi : lo2;
        unsigned c1i = (unsigned)(m1 & 0xFFFFFFFFull);
        unsigned c2i = (unsigned)(m2 & 0xFFFFFFFFull);

        const float* Rr = g_R + (size_t)(row0 + m) * FDIM;
        const float* q1 = cbl + (size_t)c1i * FDIM;
        const float* q2 = cbl + (size_t)c2i * FDIM;
        double d1 = 0.0, d2 = 0.0;
        #pragma unroll
        for (int j = 0; j < 16; ++j) {
            int k = lane + 32 * j;
            double rv = (double)Rr[k];
            d1 += rv * (double)q1[k];
            d2 += rv * (double)q2[k];
        }
        #pragma unroll
        for (int off = 16; off; off >>= 1) {
            d1 += __shfl_xor_sync(0xffffffffu, d1, off);
            d2 += __shfl_xor_sync(0xffffffffu, d2, off);
        }
        if (lane == 0) {
            float x2 = x2s[m];
            float s1 = __fsub_rn(__fadd_rn(x2, c2s[c1i]), __fmul_rn(2.0f, (float)d1));
            float s2 = __fsub_rn(__fadd_rn(x2, c2s[c2i]), __fmul_rn(2.0f, (float)d2));
            unsigned pick;
            if (s1 < s2)      pick = c1i;
            else if (s2 < s1) pick = c2i;
            else              pick = (c1i < c2i) ? c1i : c2i;
            ((unsigned*)(smem + SM_BIDX))[m] = pick;
            size_t o = (size_t)(row0 + m) * NLAYERS + layer;
            if (mode == 0)      ((float*)out_raw)[o] = (float)pick;
            else if (mode == 2) ((long long*)out_raw)[o] = (long long)pick;
        }
    }
    __syncthreads();

    // ---- residual update: warp per row; next-layer splits + x2; recon on last ----
    float* recon = (mode == 1) ? (float*)out_raw
                               : ((float*)out_raw + (size_t)nrows * NLAYERS);
    for (int m = wid; m < BM; m += 8) {
        int row = row0 + m;
        if (row >= nrows) continue;
        unsigned idx = ((unsigned*)(smem + SM_BIDX))[m];
        const float4* cbr = (const float4*)(cb + ((size_t)layer * KCODES + idx) * FDIM);
        float4* Rr = (float4*)(g_R + (size_t)row * FDIM);
        double ss = 0.0;
        #pragma unroll
        for (int j = 0; j < 4; ++j) {
            int q = lane + 32 * j;
            float4 rv = Rr[q], cv = cbr[q];
            rv.x -= cv.x; rv.y -= cv.y; rv.z -= cv.z; rv.w -= cv.w;
            Rr[q] = rv;
            if (layer == NLAYERS - 1) {
                if (mode != 2) {
                    float4 dv = ((const float4*)(data + (size_t)row * FDIM))[q];
                    float4 rc = {dv.x - rv.x, dv.y - rv.y, dv.z - rv.z, dv.w - rv.w};
                    ((float4*)(recon + (size_t)row * FDIM))[q] = rc;
                }
            } else {
                float vv[4] = {rv.x, rv.y, rv.z, rv.w};
                __nv_bfloat16 h[4], md[4], lo[4];
                #pragma unroll
                for (int c = 0; c < 4; ++c) {
                    split3(vv[c], h[c], md[c], lo[c]);
                    ss += (double)vv[c] * vv[c];
                }
                size_t e = (size_t)row * FDIM + (size_t)q * 4;
                __nv_bfloat162 t;
                t.x=h[0];  t.y=h[1];  *(__nv_bfloat162*)(g_Rhi+e)   = t;
                t.x=h[2];  t.y=h[3];  *(__nv_bfloat162*)(g_Rhi+e+2) = t;
                t.x=md[0]; t.y=md[1]; *(__nv_bfloat162*)(g_Rmd+e)   = t;
                t.x=md[2]; t.y=md[3]; *(__nv_bfloat162*)(g_Rmd+e+2) = t;
                t.x=lo[0]; t.y=lo[1]; *(__nv_bfloat162*)(g_Rlo+e)   = t;
                t.x=lo[2]; t.y=lo[3]; *(__nv_bfloat162*)(g_Rlo+e+2) = t;
            }
        }
        if (layer != NLAYERS - 1) {
            #pragma unroll
            for (int off = 16; off; off >>= 1) ss += __shfl_xor_sync(0xffffffffu, ss, off);
            if (lane == 0) g_x2[row] = (float)ss;
        }
    }
}

// ---------------- host ----------------
extern "C" void kernel_launch(void* const* d_in, const int* in_sizes, int n_in,
                              void* d_out, int out_size) {
    const float* data = (const float*)d_in[0];
    const float* cb   = (const float*)d_in[1];
    int nrows = in_sizes[0] / FDIM;

    long long n_both  = (long long)nrows * (NLAYERS + FDIM);
    long long n_recon = (long long)nrows * FDIM;
    long long n_codes = (long long)nrows * NLAYERS;
    int mode = 0;
    if ((long long)out_size == n_recon)      mode = 1;
    else if ((long long)out_size == n_codes) mode = 2;
    else if ((long long)out_size == n_both)  mode = 0;

    cudaFuncSetAttribute(layer_kernel, cudaFuncAttributeMaxDynamicSharedMemorySize,
                         SMEM_TOTAL);

    cbprep_kernel<<<(NLAYERS * KCODES * FDIM / 4 + 255) / 256, 256>>>(cb);
    c2_kernel<<<(NLAYERS * KCODES + 7) / 8, 256>>>(cb);
    init_kernel<<<(nrows + 7) / 8, 256>>>(data, nrows);

    int grid = (nrows + BM - 1) / BM;
    for (int l = 0; l < NLAYERS; ++l)
        layer_kernel<<<grid, 256, SMEM_TOTAL>>>(cb, data, d_out, nrows, l, mode);
}

// round 11
// speedup vs baseline: 2.2525x; 1.4193x over previous
#include <cuda_runtime.h>
#include <cuda_bf16.h>
#include <cstdint>

#define NLAYERS 4
#define KCODES  1024
#define FDIM    512
#define BM      128
#define BN      128
#define KT      64
#define NSTK    (FDIM / KT)      // 8 k-tiles
#define NCHUNK  (KCODES / BN)    // 8 n-chunks
#define NSTEPS  (NCHUNK * NSTK)  // 64
#define MAXR    100352
#define NTHREADS 512

// ---------------- global scratch ----------------
__device__ __align__(16) float          g_R  [(size_t)MAXR * FDIM];
__device__ __align__(16) __nv_bfloat16  g_Rhi[(size_t)MAXR * FDIM];
__device__ __align__(16) __nv_bfloat16  g_Rmd[(size_t)MAXR * FDIM];
__device__ float g_x2[MAXR];
__device__ __align__(16) __nv_bfloat16  g_Chi[NLAYERS * KCODES * FDIM];
__device__ __align__(16) __nv_bfloat16  g_Cmd[NLAYERS * KCODES * FDIM];
__device__ float g_c2[NLAYERS * KCODES];

// ---------------- helpers ----------------
__device__ __forceinline__ uint32_t smem_u32(const void* p) {
    uint32_t a;
    asm("{ .reg .u64 t; cvta.to.shared.u64 t, %1; cvt.u32.u64 %0, t; }" : "=r"(a) : "l"(p));
    return a;
}
#define SWZ128(o) ((o) ^ (((o) >> 3) & 0x70))

__device__ __forceinline__ void cp_async16(uint32_t saddr, const void* gaddr) {
    asm volatile("cp.async.cg.shared.global [%0], [%1], 16;"
                 :: "r"(saddr), "l"(gaddr) : "memory");
}
#define CP_COMMIT() asm volatile("cp.async.commit_group;" ::: "memory")
#define CP_WAIT1()  asm volatile("cp.async.wait_group 1;" ::: "memory")
#define CP_WAIT0()  asm volatile("cp.async.wait_group 0;" ::: "memory")

__device__ __forceinline__ void ldm_x4(uint32_t* r, uint32_t addr) {
    asm volatile("ldmatrix.sync.aligned.m8n8.x4.shared.b16 {%0,%1,%2,%3}, [%4];"
                 : "=r"(r[0]), "=r"(r[1]), "=r"(r[2]), "=r"(r[3]) : "r"(addr));
}
__device__ __forceinline__ void mma16816(float* c, const uint32_t* a,
                                         uint32_t b0, uint32_t b1) {
    asm volatile("mma.sync.aligned.m16n8k16.row.col.f32.bf16.bf16.f32 "
                 "{%0,%1,%2,%3}, {%4,%5,%6,%7}, {%8,%9}, {%0,%1,%2,%3};"
                 : "+f"(c[0]), "+f"(c[1]), "+f"(c[2]), "+f"(c[3])
                 : "r"(a[0]), "r"(a[1]), "r"(a[2]), "r"(a[3]), "r"(b0), "r"(b1));
}

__device__ __forceinline__ unsigned fmono(float f) {
    unsigned u = __float_as_uint(f);
    return (u & 0x80000000u) ? ~u : (u | 0x80000000u);
}
__device__ __forceinline__ void split2(float x, __nv_bfloat16& h, __nv_bfloat16& m) {
    h = __float2bfloat16(x);
    float r1 = x - __bfloat162float(h);
    m = __float2bfloat16(r1);
}

// ---------------- prep kernels ----------------
__global__ void cbprep_kernel(const float* __restrict__ cb) {
    size_t i0 = ((size_t)blockIdx.x * 256 + threadIdx.x) * 4;
    if (i0 >= (size_t)NLAYERS * KCODES * FDIM) return;
    #pragma unroll
    for (int j = 0; j < 4; ++j) {
        size_t i = i0 + j;
        __nv_bfloat16 h, m;
        split2(cb[i], h, m);
        g_Chi[i] = h; g_Cmd[i] = m;
    }
}

__global__ void c2_kernel(const float* __restrict__ cb) {
    int code = blockIdx.x * 8 + (threadIdx.x >> 5);
    int lane = threadIdx.x & 31;
    if (code >= NLAYERS * KCODES) return;
    const float* row = cb + (size_t)code * FDIM;
    double s = 0.0;
    for (int k = lane; k < FDIM; k += 32) { double v = (double)row[k]; s += v * v; }
    #pragma unroll
    for (int off = 16; off; off >>= 1) s += __shfl_xor_sync(0xffffffffu, s, off);
    if (lane == 0) g_c2[code] = (float)s;
}

__global__ void init_kernel(const float* __restrict__ data, int nrows) {
    int r = blockIdx.x * 8 + (threadIdx.x >> 5);
    int lane = threadIdx.x & 31;
    if (r >= nrows) return;
    const float4* src = (const float4*)(data + (size_t)r * FDIM);
    float4* Rr = (float4*)(g_R + (size_t)r * FDIM);
    double ss = 0.0;
    #pragma unroll
    for (int j = 0; j < 4; ++j) {
        int q = lane + 32 * j;
        float4 v = src[q];
        Rr[q] = v;
        float vv[4] = {v.x, v.y, v.z, v.w};
        __nv_bfloat16 h[4], m[4];
        #pragma unroll
        for (int c = 0; c < 4; ++c) {
            split2(vv[c], h[c], m[c]);
            ss += (double)vv[c] * vv[c];
        }
        size_t e = (size_t)r * FDIM + (size_t)q * 4;
        __nv_bfloat162 t;
        t.x=h[0]; t.y=h[1]; *(__nv_bfloat162*)(g_Rhi+e)   = t;
        t.x=h[2]; t.y=h[3]; *(__nv_bfloat162*)(g_Rhi+e+2) = t;
        t.x=m[0]; t.y=m[1]; *(__nv_bfloat162*)(g_Rmd+e)   = t;
        t.x=m[2]; t.y=m[3]; *(__nv_bfloat162*)(g_Rmd+e+2) = t;
    }
    #pragma unroll
    for (int off = 16; off; off >>= 1) ss += __shfl_xor_sync(0xffffffffu, ss, off);
    if (lane == 0) g_x2[r] = (float)ss;
}

// ---------------- layer kernel ----------------
// smem map (bytes):
//   [0,512)        x2s float[128]
//   [512,4608)     c2s float[1024]
//   [4608,12800)   top u64[128][4][2] (per row, per warp-column wn: top-2 keys)
//   [12800,13312)  bidx u32[128]
//   [13312,...)    tiles: 2 stages x 4 tiles x 16384 (Ahi, Amd, Bhi, Bmd)
#define SM_X2   0
#define SM_C2   512
#define SM_TOP  4608
#define SM_BIDX 12800
#define SM_TILE 13312
#define TILE_SZ 16384
#define TILE_OFF(stg, t) (SM_TILE + ((stg) * 4 + (t)) * TILE_SZ)
#define SMEM_TOTAL (SM_TILE + 8 * TILE_SZ)   // 144384 B

__global__ __launch_bounds__(NTHREADS, 1)
void layer_kernel(const float* __restrict__ cb, const float* __restrict__ data,
                  void* __restrict__ out_raw, int nrows, int layer, int mode) {
    extern __shared__ char smem[];
    const uint32_t sb = smem_u32(smem);
    const int tid = threadIdx.x, wid = tid >> 5, lane = tid & 31;
    const int wm = wid & 3, wn = wid >> 2;     // 4 warps M x 4 warps N (32x32 per warp)
    const int row0 = blockIdx.x * BM;

    float* x2s = (float*)(smem + SM_X2);
    float* c2s = (float*)(smem + SM_C2);
    unsigned long long* topsm = (unsigned long long*)(smem + SM_TOP);

    for (int i = tid; i < KCODES; i += NTHREADS) c2s[i] = g_c2[layer * KCODES + i];
    if (tid < BM) {
        int r = min(row0 + tid, nrows - 1);
        x2s[tid] = g_x2[r];
    }
    __syncthreads();

    // tiles: 0=Ahi 1=Amd 2=Bhi 3=Bmd
    const __nv_bfloat16* tsrc[4] = {g_Rhi, g_Rmd, g_Chi, g_Cmd};

    auto load_stage = [&](int stg, int chunk, int ktile) {
        const int n0 = chunk * BN;
        #pragma unroll
        for (int t = 0; t < 4; ++t) {
            const __nv_bfloat16* src = tsrc[t];
            const uint32_t base = sb + TILE_OFF(stg, t);
            #pragma unroll
            for (int j = 0; j < 2; ++j) {
                int i = tid + NTHREADS * j;
                int row = i >> 3, c16 = i & 7;
                int rg = (t < 2) ? min(row0 + row, nrows - 1)
                                 : (layer * KCODES + n0 + row);
                const void* g = src + (size_t)rg * FDIM + ktile * KT + c16 * 8;
                cp_async16(base + SWZ128(row * 128 + c16 * 16), g);
            }
        }
    };

    float acc[2][4][4];
    #pragma unroll
    for (int mf = 0; mf < 2; ++mf)
        #pragma unroll
        for (int nf = 0; nf < 4; ++nf)
            #pragma unroll
            for (int q = 0; q < 4; ++q) acc[mf][nf][q] = 0.f;

    // per-lane running top-2 for 4 row-slots: s = mf*2 + (0:rowA, 1:rowB)
    unsigned long long tk1[4], tk2[4];
    #pragma unroll
    for (int s = 0; s < 4; ++s) { tk1[s] = ~0ull; tk2[s] = ~0ull; }

    load_stage(0, 0, 0);
    CP_COMMIT();

    // 3 split products: hh, hm, mh  (A tile, B tile)
    const int ca3[3] = {0, 0, 1};
    const int cb3[3] = {2, 3, 2};

    for (int step = 0; step < NSTEPS; ++step) {
        const int chunk = step >> 3, ktile = step & 7, stg = step & 1;
        if (step + 1 < NSTEPS) {
            load_stage(stg ^ 1, (step + 1) >> 3, (step + 1) & 7);
            CP_COMMIT();
            CP_WAIT1();
        } else {
            CP_WAIT0();
        }
        __syncthreads();

        #pragma unroll
        for (int c3 = 0; c3 < 3; ++c3) {
            const uint32_t abase = sb + TILE_OFF(stg, ca3[c3]);
            const uint32_t bbase = sb + TILE_OFF(stg, cb3[c3]);
            #pragma unroll
            for (int ks = 0; ks < 4; ++ks) {
                uint32_t afr[2][4];
                #pragma unroll
                for (int mf = 0; mf < 2; ++mf) {
                    int arow = wm * 32 + mf * 16 + (lane & 15);
                    int akc  = ks * 2 + (lane >> 4);
                    ldm_x4(afr[mf], abase + SWZ128(arow * 128 + akc * 16));
                }
                #pragma unroll
                for (int nf2 = 0; nf2 < 2; ++nf2) {
                    uint32_t bfr[4];
                    int g = lane >> 3;
                    int brow = wn * 32 + nf2 * 16 + ((g >> 1) << 3) + (lane & 7);
                    int bkc  = ks * 2 + (g & 1);
                    ldm_x4(bfr, bbase + SWZ128(brow * 128 + bkc * 16));
                    mma16816(acc[0][nf2 * 2 + 0], afr[0], bfr[0], bfr[1]);
                    mma16816(acc[0][nf2 * 2 + 1], afr[0], bfr[2], bfr[3]);
                    mma16816(acc[1][nf2 * 2 + 0], afr[1], bfr[0], bfr[1]);
                    mma16816(acc[1][nf2 * 2 + 1], afr[1], bfr[2], bfr[3]);
                }
            }
        }

        // ---- per-chunk epilogue: approx score, fold per-lane top-2 ----
        if (ktile == 7) {
            const int n0 = chunk * BN;
            #pragma unroll
            for (int mf = 0; mf < 2; ++mf) {
                int rA = wm * 32 + mf * 16 + (lane >> 2);
                int rB = rA + 8;
                float x2A = x2s[rA], x2B = x2s[rB];
                #pragma unroll
                for (int nf = 0; nf < 4; ++nf) {
                    int col = wn * 32 + nf * 8 + (lane & 3) * 2;
                    #pragma unroll
                    for (int e = 0; e < 2; ++e) {
                        int idxc = n0 + col + e;
                        float cc = c2s[idxc];
                        float scA = __fsub_rn(__fadd_rn(x2A, cc),
                                              __fmul_rn(2.0f, acc[mf][nf][e]));
                        float scB = __fsub_rn(__fadd_rn(x2B, cc),
                                              __fmul_rn(2.0f, acc[mf][nf][2 + e]));
                        unsigned long long keyA =
                            ((unsigned long long)fmono(scA) << 32) | (unsigned)idxc;
                        unsigned long long keyB =
                            ((unsigned long long)fmono(scB) << 32) | (unsigned)idxc;
                        int sA = mf * 2, sB = mf * 2 + 1;
                        if (keyA < tk1[sA]) { tk2[sA] = tk1[sA]; tk1[sA] = keyA; }
                        else if (keyA < tk2[sA]) tk2[sA] = keyA;
                        if (keyB < tk1[sB]) { tk2[sB] = tk1[sB]; tk1[sB] = keyB; }
                        else if (keyB < tk2[sB]) tk2[sB] = keyB;
                    }
                }
                #pragma unroll
                for (int nf = 0; nf < 4; ++nf)
                    #pragma unroll
                    for (int q = 0; q < 4; ++q) acc[mf][nf][q] = 0.f;
            }
        }
        __syncthreads();
    }

    // ---- quad merge of per-lane top-2 -> smem per (row, wn) ----
    #pragma unroll
    for (int s = 0; s < 4; ++s) {
        unsigned long long a = tk1[s], b = tk2[s];
        #pragma unroll
        for (int off = 1; off <= 2; off <<= 1) {
            unsigned long long oa = __shfl_xor_sync(0xffffffffu, a, off);
            unsigned long long ob = __shfl_xor_sync(0xffffffffu, b, off);
            unsigned long long n1 = (a < oa) ? a : oa;
            unsigned long long hi = (a < oa) ? oa : a;
            unsigned long long lo2 = (b < ob) ? b : ob;
            b = (hi < lo2) ? hi : lo2;
            a = n1;
        }
        if ((lane & 3) == 0) {
            int row = wm * 32 + (s >> 1) * 16 + (lane >> 2) + (s & 1) * 8;
            topsm[row * 8 + wn * 2 + 0] = a;
            topsm[row * 8 + wn * 2 + 1] = b;
        }
    }
    __syncthreads();

    // ---- fp64 exact rescore of top-2 candidates (warp per row) ----
    const float* cbl = cb + (size_t)layer * KCODES * FDIM;
    for (int m = wid; m < BM; m += 16) {
        if (row0 + m >= nrows) continue;
        unsigned long long k1 = ~0ull, k2 = ~0ull;
        #pragma unroll
        for (int i = 0; i < 8; ++i) {
            unsigned long long v = topsm[m * 8 + i];
            if (v < k1) { k2 = k1; k1 = v; }
            else if (v < k2) k2 = v;
        }
        unsigned c1i = (unsigned)(k1 & 0xFFFFFFFFull);
        unsigned c2i = (unsigned)(k2 & 0xFFFFFFFFull);

        const float* Rr = g_R + (size_t)(row0 + m) * FDIM;
        const float* q1 = cbl + (size_t)c1i * FDIM;
        const float* q2 = cbl + (size_t)c2i * FDIM;
        double d1 = 0.0, d2 = 0.0;
        #pragma unroll
        for (int j = 0; j < 16; ++j) {
            int k = lane + 32 * j;
            double rv = (double)Rr[k];
            d1 += rv * (double)q1[k];
            d2 += rv * (double)q2[k];
        }
        #pragma unroll
        for (int off = 16; off; off >>= 1) {
            d1 += __shfl_xor_sync(0xffffffffu, d1, off);
            d2 += __shfl_xor_sync(0xffffffffu, d2, off);
        }
        if (lane == 0) {
            float x2 = x2s[m];
            float s1 = __fsub_rn(__fadd_rn(x2, c2s[c1i]), __fmul_rn(2.0f, (float)d1));
            float s2 = __fsub_rn(__fadd_rn(x2, c2s[c2i]), __fmul_rn(2.0f, (float)d2));
            unsigned pick;
            if (s1 < s2)      pick = c1i;
            else if (s2 < s1) pick = c2i;
            else              pick = (c1i < c2i) ? c1i : c2i;
            ((unsigned*)(smem + SM_BIDX))[m] = pick;
            size_t o = (size_t)(row0 + m) * NLAYERS + layer;
            if (mode == 0)      ((float*)out_raw)[o] = (float)pick;
            else if (mode == 2) ((long long*)out_raw)[o] = (long long)pick;
        }
    }
    __syncthreads();

    // ---- residual update: warp per row; next-layer splits + x2; recon on last ----
    float* recon = (mode == 1) ? (float*)out_raw
                               : ((float*)out_raw + (size_t)nrows * NLAYERS);
    for (int m = wid; m < BM; m += 16) {
        int row = row0 + m;
        if (row >= nrows) continue;
        unsigned idx = ((unsigned*)(smem + SM_BIDX))[m];
        const float4* cbr = (const float4*)(cb + ((size_t)layer * KCODES + idx) * FDIM);
        float4* Rr = (float4*)(g_R + (size_t)row * FDIM);
        double ss = 0.0;
        #pragma unroll
        for (int j = 0; j < 4; ++j) {
            int q = lane + 32 * j;
            float4 rv = Rr[q], cv = cbr[q];
            rv.x -= cv.x; rv.y -= cv.y; rv.z -= cv.z; rv.w -= cv.w;
            Rr[q] = rv;
            if (layer == NLAYERS - 1) {
                if (mode != 2) {
                    float4 dv = ((const float4*)(data + (size_t)row * FDIM))[q];
                    float4 rc = {dv.x - rv.x, dv.y - rv.y, dv.z - rv.z, dv.w - rv.w};
                    ((float4*)(recon + (size_t)row * FDIM))[q] = rc;
                }
            } else {
                float vv[4] = {rv.x, rv.y, rv.z, rv.w};
                __nv_bfloat16 h[4], md[4];
                #pragma unroll
                for (int c = 0; c < 4; ++c) {
                    split2(vv[c], h[c], md[c]);
                    ss += (double)vv[c] * vv[c];
                }
                size_t e = (size_t)row * FDIM + (size_t)q * 4;
                __nv_bfloat162 t;
                t.x=h[0];  t.y=h[1];  *(__nv_bfloat162*)(g_Rhi+e)   = t;
                t.x=h[2];  t.y=h[3];  *(__nv_bfloat162*)(g_Rhi+e+2) = t;
                t.x=md[0]; t.y=md[1]; *(__nv_bfloat162*)(g_Rmd+e)   = t;
                t.x=md[2]; t.y=md[3]; *(__nv_bfloat162*)(g_Rmd+e+2) = t;
            }
        }
        if (layer != NLAYERS - 1) {
            #pragma unroll
            for (int off = 16; off; off >>= 1) ss += __shfl_xor_sync(0xffffffffu, ss, off);
            if (lane == 0) g_x2[row] = (float)ss;
        }
    }
}

// ---------------- host ----------------
extern "C" void kernel_launch(void* const* d_in, const int* in_sizes, int n_in,
                              void* d_out, int out_size) {
    const float* data = (const float*)d_in[0];
    const float* cb   = (const float*)d_in[1];
    int nrows = in_sizes[0] / FDIM;

    long long n_both  = (long long)nrows * (NLAYERS + FDIM);
    long long n_recon = (long long)nrows * FDIM;
    long long n_codes = (long long)nrows * NLAYERS;
    int mode = 0;
    if ((long long)out_size == n_recon)      mode = 1;
    else if ((long long)out_size == n_codes) mode = 2;
    else if ((long long)out_size == n_both)  mode = 0;

    cudaFuncSetAttribute(layer_kernel, cudaFuncAttributeMaxDynamicSharedMemorySize,
                         SMEM_TOTAL);

    cbprep_kernel<<<(NLAYERS * KCODES * FDIM / 4 + 255) / 256, 256>>>(cb);
    c2_kernel<<<(NLAYERS * KCODES + 7) / 8, 256>>>(cb);
    init_kernel<<<(nrows + 7) / 8, 256>>>(data, nrows);

    int grid = (nrows + BM - 1) / BM;
    for (int l = 0; l < NLAYERS; ++l)
        layer_kernel<<<grid, NTHREADS, SMEM_TOTAL>>>(cb, data, d_out, nrows, l, mode);
}

// round 12
// speedup vs baseline: 3.4882x; 1.5486x over previous
#include <cuda_runtime.h>
#include <cuda_bf16.h>
#include <cstdint>

#define NLAYERS 4
#define KCODES  1024
#define FDIM    512
#define BM      128
#define BN      64
#define KT      64
#define NSTK    (FDIM / KT)      // 8 k-tiles
#define NCHUNK  (KCODES / BN)    // 16 n-chunks
#define NSTEPS  (NCHUNK * NSTK)  // 128
#define MAXR    100352
#define NTHREADS 256

// ---------------- global scratch ----------------
__device__ __align__(16) float          g_R  [(size_t)MAXR * FDIM];
__device__ __align__(16) __nv_bfloat16  g_Rhi[(size_t)MAXR * FDIM];
__device__ __align__(16) __nv_bfloat16  g_Rmd[(size_t)MAXR * FDIM];
__device__ float g_x2[MAXR];
__device__ __align__(16) __nv_bfloat16  g_Chi[NLAYERS * KCODES * FDIM];
__device__ __align__(16) __nv_bfloat16  g_Cmd[NLAYERS * KCODES * FDIM];
__device__ float g_c2[NLAYERS * KCODES];

// ---------------- helpers ----------------
__device__ __forceinline__ uint32_t smem_u32(const void* p) {
    uint32_t a;
    asm("{ .reg .u64 t; cvta.to.shared.u64 t, %1; cvt.u32.u64 %0, t; }" : "=r"(a) : "l"(p));
    return a;
}
#define SWZ128(o) ((o) ^ (((o) >> 3) & 0x70))

__device__ __forceinline__ void cp_async16(uint32_t saddr, const void* gaddr) {
    asm volatile("cp.async.cg.shared.global [%0], [%1], 16;"
                 :: "r"(saddr), "l"(gaddr) : "memory");
}
#define CP_COMMIT() asm volatile("cp.async.commit_group;" ::: "memory")
#define CP_WAIT1()  asm volatile("cp.async.wait_group 1;" ::: "memory")
#define CP_WAIT0()  asm volatile("cp.async.wait_group 0;" ::: "memory")

__device__ __forceinline__ void ldm_x4(uint32_t* r, uint32_t addr) {
    asm volatile("ldmatrix.sync.aligned.m8n8.x4.shared.b16 {%0,%1,%2,%3}, [%4];"
                 : "=r"(r[0]), "=r"(r[1]), "=r"(r[2]), "=r"(r[3]) : "r"(addr));
}
__device__ __forceinline__ void mma16816(float* c, const uint32_t* a,
                                         uint32_t b0, uint32_t b1) {
    asm volatile("mma.sync.aligned.m16n8k16.row.col.f32.bf16.bf16.f32 "
                 "{%0,%1,%2,%3}, {%4,%5,%6,%7}, {%8,%9}, {%0,%1,%2,%3};"
                 : "+f"(c[0]), "+f"(c[1]), "+f"(c[2]), "+f"(c[3])
                 : "r"(a[0]), "r"(a[1]), "r"(a[2]), "r"(a[3]), "r"(b0), "r"(b1));
}

__device__ __forceinline__ unsigned fmono(float f) {
    unsigned u = __float_as_uint(f);
    return (u & 0x80000000u) ? ~u : (u | 0x80000000u);
}
__device__ __forceinline__ void split2(float x, __nv_bfloat16& h, __nv_bfloat16& m) {
    h = __float2bfloat16(x);
    float r1 = x - __bfloat162float(h);
    m = __float2bfloat16(r1);
}

// ---------------- prep kernels ----------------
__global__ void cbprep_kernel(const float* __restrict__ cb) {
    size_t i0 = ((size_t)blockIdx.x * 256 + threadIdx.x) * 4;
    if (i0 >= (size_t)NLAYERS * KCODES * FDIM) return;
    #pragma unroll
    for (int j = 0; j < 4; ++j) {
        size_t i = i0 + j;
        __nv_bfloat16 h, m;
        split2(cb[i], h, m);
        g_Chi[i] = h; g_Cmd[i] = m;
    }
}

__global__ void c2_kernel(const float* __restrict__ cb) {
    int code = blockIdx.x * 8 + (threadIdx.x >> 5);
    int lane = threadIdx.x & 31;
    if (code >= NLAYERS * KCODES) return;
    const float* row = cb + (size_t)code * FDIM;
    double s = 0.0;
    for (int k = lane; k < FDIM; k += 32) { double v = (double)row[k]; s += v * v; }
    #pragma unroll
    for (int off = 16; off; off >>= 1) s += __shfl_xor_sync(0xffffffffu, s, off);
    if (lane == 0) g_c2[code] = (float)s;
}

__global__ void init_kernel(const float* __restrict__ data, int nrows) {
    int r = blockIdx.x * 8 + (threadIdx.x >> 5);
    int lane = threadIdx.x & 31;
    if (r >= nrows) return;
    const float4* src = (const float4*)(data + (size_t)r * FDIM);
    float4* Rr = (float4*)(g_R + (size_t)r * FDIM);
    double ss = 0.0;
    #pragma unroll
    for (int j = 0; j < 4; ++j) {
        int q = lane + 32 * j;
        float4 v = src[q];
        Rr[q] = v;
        float vv[4] = {v.x, v.y, v.z, v.w};
        __nv_bfloat16 h[4], m[4];
        #pragma unroll
        for (int c = 0; c < 4; ++c) {
            split2(vv[c], h[c], m[c]);
            ss += (double)vv[c] * vv[c];
        }
        size_t e = (size_t)r * FDIM + (size_t)q * 4;
        __nv_bfloat162 t;
        t.x=h[0]; t.y=h[1]; *(__nv_bfloat162*)(g_Rhi+e)   = t;
        t.x=h[2]; t.y=h[3]; *(__nv_bfloat162*)(g_Rhi+e+2) = t;
        t.x=m[0]; t.y=m[1]; *(__nv_bfloat162*)(g_Rmd+e)   = t;
        t.x=m[2]; t.y=m[3]; *(__nv_bfloat162*)(g_Rmd+e+2) = t;
    }
    #pragma unroll
    for (int off = 16; off; off >>= 1) ss += __shfl_xor_sync(0xffffffffu, ss, off);
    if (lane == 0) g_x2[r] = (float)ss;
}

// ---------------- layer kernel ----------------
// smem map (bytes):
//   [0,512)       x2s float[128]
//   [512,4608)    c2s float[1024]
//   [4608,8704)   top u64[128][2][2]
//   [8704,9216)   bidx u32[128]
//   [9216,...)    tiles: 2 stages x (Ahi 16K | Amd 16K | Bhi 8K | Bmd 8K)
#define SM_X2    0
#define SM_C2    512
#define SM_TOP   4608
#define SM_BIDX  8704
#define SM_TILE  9216
#define STAGE_SZ 49152
#define SMEM_TOTAL (SM_TILE + 2 * STAGE_SZ)   // 107520 B -> 2 CTAs/SM

__global__ __launch_bounds__(NTHREADS, 2)
void layer_kernel(const float* __restrict__ cb, const float* __restrict__ data,
                  void* __restrict__ out_raw, int nrows, int layer, int mode) {
    extern __shared__ char smem[];
    const uint32_t sb = smem_u32(smem);
    const int tid = threadIdx.x, wid = tid >> 5, lane = tid & 31;
    const int wm = wid & 3, wn = wid >> 2;     // 4 warps M x 2 warps N (32x32 per warp)
    const int row0 = blockIdx.x * BM;

    float* x2s = (float*)(smem + SM_X2);
    float* c2s = (float*)(smem + SM_C2);
    unsigned long long* topsm = (unsigned long long*)(smem + SM_TOP);

    for (int i = tid; i < KCODES; i += NTHREADS) c2s[i] = g_c2[layer * KCODES + i];
    if (tid < BM) {
        int r = min(row0 + tid, nrows - 1);
        x2s[tid] = g_x2[r];
    }
    __syncthreads();

    auto load_stage = [&](int stg, int chunk, int ktile) {
        const int n0 = chunk * BN;
        const uint32_t sbase = sb + SM_TILE + stg * STAGE_SZ;
        // A tiles: 128 rows x 128B each
        #pragma unroll
        for (int t = 0; t < 2; ++t) {
            const __nv_bfloat16* src = (t == 0) ? g_Rhi : g_Rmd;
            const uint32_t base = sbase + t * 16384;
            #pragma unroll
            for (int j = 0; j < 4; ++j) {
                int i = tid + NTHREADS * j;
                int row = i >> 3, c16 = i & 7;
                int rg = min(row0 + row, nrows - 1);
                cp_async16(base + SWZ128(row * 128 + c16 * 16),
                           src + (size_t)rg * FDIM + ktile * KT + c16 * 8);
            }
        }
        // B tiles: 64 rows x 128B each
        #pragma unroll
        for (int t = 0; t < 2; ++t) {
            const __nv_bfloat16* src = (t == 0) ? g_Chi : g_Cmd;
            const uint32_t base = sbase + 32768 + t * 8192;
            #pragma unroll
            for (int j = 0; j < 2; ++j) {
                int i = tid + NTHREADS * j;
                int row = i >> 3, c16 = i & 7;
                int rg = layer * KCODES + n0 + row;
                cp_async16(base + SWZ128(row * 128 + c16 * 16),
                           src + (size_t)rg * FDIM + ktile * KT + c16 * 8);
            }
        }
    };

    float acc[2][4][4];
    #pragma unroll
    for (int mf = 0; mf < 2; ++mf)
        #pragma unroll
        for (int nf = 0; nf < 4; ++nf)
            #pragma unroll
            for (int q = 0; q < 4; ++q) acc[mf][nf][q] = 0.f;

    unsigned long long tk1[4], tk2[4];
    #pragma unroll
    for (int s = 0; s < 4; ++s) { tk1[s] = ~0ull; tk2[s] = ~0ull; }

    load_stage(0, 0, 0);
    CP_COMMIT();

    for (int step = 0; step < NSTEPS; ++step) {
        const int chunk = step >> 3, ktile = step & 7, stg = step & 1;
        if (step + 1 < NSTEPS) {
            load_stage(stg ^ 1, (step + 1) >> 3, (step + 1) & 7);
            CP_COMMIT();
            CP_WAIT1();
        } else {
            CP_WAIT0();
        }
        __syncthreads();

        const uint32_t sbase = sb + SM_TILE + stg * STAGE_SZ;
        const uint32_t ahiB = sbase, amdB = sbase + 16384;
        const uint32_t bhiB = sbase + 32768, bmdB = sbase + 40960;

        #pragma unroll
        for (int ks = 0; ks < 4; ++ks) {
            // cached fragments: 8 LDSM feed 24 MMAs
            uint32_t ah[2][4], am[2][4], bh[2][4], bm[2][4];
            #pragma unroll
            for (int mf = 0; mf < 2; ++mf) {
                int arow = wm * 32 + mf * 16 + (lane & 15);
                int akc  = ks * 2 + (lane >> 4);
                uint32_t aoff = SWZ128(arow * 128 + akc * 16);
                ldm_x4(ah[mf], ahiB + aoff);
                ldm_x4(am[mf], amdB + aoff);
            }
            #pragma unroll
            for (int nf2 = 0; nf2 < 2; ++nf2) {
                int g = lane >> 3;
                int brow = wn * 32 + nf2 * 16 + ((g >> 1) << 3) + (lane & 7);
                int bkc  = ks * 2 + (g & 1);
                uint32_t boff = SWZ128(brow * 128 + bkc * 16);
                ldm_x4(bh[nf2], bhiB + boff);
                ldm_x4(bm[nf2], bmdB + boff);
            }
            #pragma unroll
            for (int mf = 0; mf < 2; ++mf)
                #pragma unroll
                for (int nf2 = 0; nf2 < 2; ++nf2) {
                    float* a0 = acc[mf][nf2 * 2 + 0];
                    float* a1 = acc[mf][nf2 * 2 + 1];
                    mma16816(a0, ah[mf], bh[nf2][0], bh[nf2][1]);   // hh
                    mma16816(a1, ah[mf], bh[nf2][2], bh[nf2][3]);
                    mma16816(a0, ah[mf], bm[nf2][0], bm[nf2][1]);   // hm
                    mma16816(a1, ah[mf], bm[nf2][2], bm[nf2][3]);
                    mma16816(a0, am[mf], bh[nf2][0], bh[nf2][1]);   // mh
                    mma16816(a1, am[mf], bh[nf2][2], bh[nf2][3]);
                }
        }

        // ---- per-chunk epilogue: approx score, fold per-lane top-2 ----
        if (ktile == 7) {
            const int n0 = chunk * BN;
            #pragma unroll
            for (int mf = 0; mf < 2; ++mf) {
                int rA = wm * 32 + mf * 16 + (lane >> 2);
                int rB = rA + 8;
                float x2A = x2s[rA], x2B = x2s[rB];
                #pragma unroll
                for (int nf = 0; nf < 4; ++nf) {
                    int col = wn * 32 + nf * 8 + (lane & 3) * 2;
                    #pragma unroll
                    for (int e = 0; e < 2; ++e) {
                        int idxc = n0 + col + e;
                        float cc = c2s[idxc];
                        float scA = __fsub_rn(__fadd_rn(x2A, cc),
                                              __fmul_rn(2.0f, acc[mf][nf][e]));
                        float scB = __fsub_rn(__fadd_rn(x2B, cc),
                                              __fmul_rn(2.0f, acc[mf][nf][2 + e]));
                        unsigned long long keyA =
                            ((unsigned long long)fmono(scA) << 32) | (unsigned)idxc;
                        unsigned long long keyB =
                            ((unsigned long long)fmono(scB) << 32) | (unsigned)idxc;
                        int sA = mf * 2, sB = mf * 2 + 1;
                        if (keyA < tk1[sA]) { tk2[sA] = tk1[sA]; tk1[sA] = keyA; }
                        else if (keyA < tk2[sA]) tk2[sA] = keyA;
                        if (keyB < tk1[sB]) { tk2[sB] = tk1[sB]; tk1[sB] = keyB; }
                        else if (keyB < tk2[sB]) tk2[sB] = keyB;
                    }
                }
                #pragma unroll
                for (int nf = 0; nf < 4; ++nf)
                    #pragma unroll
                    for (int q = 0; q < 4; ++q) acc[mf][nf][q] = 0.f;
            }
        }
        __syncthreads();
    }

    // ---- quad merge of per-lane top-2 -> smem per (row, wn) ----
    #pragma unroll
    for (int s = 0; s < 4; ++s) {
        unsigned long long a = tk1[s], b = tk2[s];
        #pragma unroll
        for (int off = 1; off <= 2; off <<= 1) {
            unsigned long long oa = __shfl_xor_sync(0xffffffffu, a, off);
            unsigned long long ob = __shfl_xor_sync(0xffffffffu, b, off);
            unsigned long long n1 = (a < oa) ? a : oa;
            unsigned long long hi = (a < oa) ? oa : a;
            unsigned long long lo2 = (b < ob) ? b : ob;
            b = (hi < lo2) ? hi : lo2;
            a = n1;
        }
        if ((lane & 3) == 0) {
            int row = wm * 32 + (s >> 1) * 16 + (lane >> 2) + (s & 1) * 8;
            topsm[row * 4 + wn * 2 + 0] = a;
            topsm[row * 4 + wn * 2 + 1] = b;
        }
    }
    __syncthreads();

    // ---- fp64 exact rescore of top-2 candidates (warp per row) ----
    const float* cbl = cb + (size_t)layer * KCODES * FDIM;
    for (int m = wid; m < BM; m += 8) {
        if (row0 + m >= nrows) continue;
        unsigned long long k1 = ~0ull, k2 = ~0ull;
        #pragma unroll
        for (int i = 0; i < 4; ++i) {
            unsigned long long v = topsm[m * 4 + i];
            if (v < k1) { k2 = k1; k1 = v; }
            else if (v < k2) k2 = v;
        }
        unsigned c1i = (unsigned)(k1 & 0xFFFFFFFFull);
        unsigned c2i = (unsigned)(k2 & 0xFFFFFFFFull);

        const float* Rr = g_R + (size_t)(row0 + m) * FDIM;
        const float* q1 = cbl + (size_t)c1i * FDIM;
        const float* q2 = cbl + (size_t)c2i * FDIM;
        double d1 = 0.0, d2 = 0.0;
        #pragma unroll
        for (int j = 0; j < 16; ++j) {
            int k = lane + 32 * j;
            double rv = (double)Rr[k];
            d1 += rv * (double)q1[k];
            d2 += rv * (double)q2[k];
        }
        #pragma unroll
        for (int off = 16; off; off >>= 1) {
            d1 += __shfl_xor_sync(0xffffffffu, d1, off);
            d2 += __shfl_xor_sync(0xffffffffu, d2, off);
        }
        if (lane == 0) {
            float x2 = x2s[m];
            float s1 = __fsub_rn(__fadd_rn(x2, c2s[c1i]), __fmul_rn(2.0f, (float)d1));
            float s2 = __fsub_rn(__fadd_rn(x2, c2s[c2i]), __fmul_rn(2.0f, (float)d2));
            unsigned pick;
            if (s1 < s2)      pick = c1i;
            else if (s2 < s1) pick = c2i;
            else              pick = (c1i < c2i) ? c1i : c2i;
            ((unsigned*)(smem + SM_BIDX))[m] = pick;
            size_t o = (size_t)(row0 + m) * NLAYERS + layer;
            if (mode == 0)      ((float*)out_raw)[o] = (float)pick;
            else if (mode == 2) ((long long*)out_raw)[o] = (long long)pick;
        }
    }
    __syncthreads();

    // ---- residual update: warp per row; next-layer splits + x2; recon on last ----
    float* recon = (mode == 1) ? (float*)out_raw
                               : ((float*)out_raw + (size_t)nrows * NLAYERS);
    for (int m = wid; m < BM; m += 8) {
        int row = row0 + m;
        if (row >= nrows) continue;
        unsigned idx = ((unsigned*)(smem + SM_BIDX))[m];
        const float4* cbr = (const float4*)(cb + ((size_t)layer * KCODES + idx) * FDIM);
        float4* Rr = (float4*)(g_R + (size_t)row * FDIM);
        double ss = 0.0;
        #pragma unroll
        for (int j = 0; j < 4; ++j) {
            int q = lane + 32 * j;
            float4 rv = Rr[q], cv = cbr[q];
            rv.x -= cv.x; rv.y -= cv.y; rv.z -= cv.z; rv.w -= cv.w;
            Rr[q] = rv;
            if (layer == NLAYERS - 1) {
                if (mode != 2) {
                    float4 dv = ((const float4*)(data + (size_t)row * FDIM))[q];
                    float4 rc = {dv.x - rv.x, dv.y - rv.y, dv.z - rv.z, dv.w - rv.w};
                    ((float4*)(recon + (size_t)row * FDIM))[q] = rc;
                }
            } else {
                float vv[4] = {rv.x, rv.y, rv.z, rv.w};
                __nv_bfloat16 h[4], md[4];
                #pragma unroll
                for (int c = 0; c < 4; ++c) {
                    split2(vv[c], h[c], md[c]);
                    ss += (double)vv[c] * vv[c];
                }
                size_t e = (size_t)row * FDIM + (size_t)q * 4;
                __nv_bfloat162 t;
                t.x=h[0];  t.y=h[1];  *(__nv_bfloat162*)(g_Rhi+e)   = t;
                t.x=h[2];  t.y=h[3];  *(__nv_bfloat162*)(g_Rhi+e+2) = t;
                t.x=md[0]; t.y=md[1]; *(__nv_bfloat162*)(g_Rmd+e)   = t;
                t.x=md[2]; t.y=md[3]; *(__nv_bfloat162*)(g_Rmd+e+2) = t;
            }
        }
        if (layer != NLAYERS - 1) {
            #pragma unroll
            for (int off = 16; off; off >>= 1) ss += __shfl_xor_sync(0xffffffffu, ss, off);
            if (lane == 0) g_x2[row] = (float)ss;
        }
    }
}

// ---------------- host ----------------
extern "C" void kernel_launch(void* const* d_in, const int* in_sizes, int n_in,
                              void* d_out, int out_size) {
    const float* data = (const float*)d_in[0];
    const float* cb   = (const float*)d_in[1];
    int nrows = in_sizes[0] / FDIM;

    long long n_both  = (long long)nrows * (NLAYERS + FDIM);
    long long n_recon = (long long)nrows * FDIM;
    long long n_codes = (long long)nrows * NLAYERS;
    int mode = 0;
    if ((long long)out_size == n_recon)      mode = 1;
    else if ((long long)out_size == n_codes) mode = 2;
    else if ((long long)out_size == n_both)  mode = 0;

    cudaFuncSetAttribute(layer_kernel, cudaFuncAttributeMaxDynamicSharedMemorySize,
                         SMEM_TOTAL);

    cbprep_kernel<<<(NLAYERS * KCODES * FDIM / 4 + 255) / 256, 256>>>(cb);
    c2_kernel<<<(NLAYERS * KCODES + 7) / 8, 256>>>(cb);
    init_kernel<<<(nrows + 7) / 8, 256>>>(data, nrows);

    int grid = (nrows + BM - 1) / BM;
    for (int l = 0; l < NLAYERS; ++l)
        layer_kernel<<<grid, NTHREADS, SMEM_TOTAL>>>(cb, data, d_out, nrows, l, mode);
}